// round 1
// baseline (speedup 1.0000x reference)
#include <cuda_runtime.h>
#include <math.h>
#include <stdint.h>

// ---------------- problem constants ----------------
#define U_LEN   2048
#define B_SZ    16
#define D_SZ    512
#define R_LEN   512
#define T_LEN   2560                 // R + U
#define M_ROWS  40960                // T_LEN * B
#define CS      30                   // cache size
#define KSZ     31
#define SPLIT_M 8192                 // R_LEN * B : rows below come from right_context

// output offsets (floats)
#define OUT_UTT_BASE   0
#define OUT_RC_BASE    16777216      // U*B*D
#define OUT_CACHE_BASE 20971520      // + R*B*D

// ---------------- scratch ----------------
__device__ float g_y  [(size_t)M_ROWS * 1024];  // GEMM1 output (a|g)
__device__ float g_glu[(size_t)M_ROWS * D_SZ];  // GLU output, [t][b][d]
__device__ float g_z  [(size_t)M_ROWS * D_SZ];  // post-depthwise + SiLU, [t][b][d]

// ---------------- SGEMM: C[m][n] = A[m][:] . W[n][:] + bias[n] ----------------
#define BM 128
#define BN 128
#define BK 8

// PHASE 0: A = (rc | utt) split at SPLIT_M, N=1024, write g_y
// PHASE 1: A = g_z, N=512, write split outputs into d_out
template<int PHASE>
__global__ __launch_bounds__(256) void sgemm_kernel(
    const float* __restrict__ A0, const float* __restrict__ A1,
    const float* __restrict__ W,  const float* __restrict__ bias,
    float* __restrict__ outp)
{
    const int N = (PHASE == 0) ? 1024 : 512;
    const int K = 512;
    __shared__ float As[BK][BM];
    __shared__ float Bs[BK][BN];

    const int m0 = blockIdx.y * BM;
    const int n0 = blockIdx.x * BN;

    const float* A;
    if (PHASE == 0) {
        A = (m0 < SPLIT_M) ? (A0 + (size_t)m0 * K)
                           : (A1 + (size_t)(m0 - SPLIT_M) * K);
    } else {
        A = g_z + (size_t)m0 * K;
    }
    const float* Wp = W + (size_t)n0 * K;

    const int tid  = threadIdx.x;
    const int lrow = tid >> 1;          // 0..127
    const int lc4  = (tid & 1) * 4;     // 0 or 4
    const int tx   = tid & 15;          // 0..15 (col group)
    const int ty   = tid >> 4;          // 0..15 (row group)

    float acc[8][8];
#pragma unroll
    for (int i = 0; i < 8; i++)
#pragma unroll
        for (int j = 0; j < 8; j++) acc[i][j] = 0.f;

    for (int k0 = 0; k0 < K; k0 += BK) {
        float4 av = *(const float4*)(A  + (size_t)lrow * K + k0 + lc4);
        float4 wv = *(const float4*)(Wp + (size_t)lrow * K + k0 + lc4);
        As[lc4 + 0][lrow] = av.x; As[lc4 + 1][lrow] = av.y;
        As[lc4 + 2][lrow] = av.z; As[lc4 + 3][lrow] = av.w;
        Bs[lc4 + 0][lrow] = wv.x; Bs[lc4 + 1][lrow] = wv.y;
        Bs[lc4 + 2][lrow] = wv.z; Bs[lc4 + 3][lrow] = wv.w;
        __syncthreads();

#pragma unroll
        for (int k = 0; k < BK; k++) {
            float4 a0 = *(const float4*)&As[k][ty * 8];
            float4 a1 = *(const float4*)&As[k][ty * 8 + 4];
            float4 b0 = *(const float4*)&Bs[k][tx * 8];
            float4 b1 = *(const float4*)&Bs[k][tx * 8 + 4];
            float af[8] = {a0.x, a0.y, a0.z, a0.w, a1.x, a1.y, a1.z, a1.w};
            float bf[8] = {b0.x, b0.y, b0.z, b0.w, b1.x, b1.y, b1.z, b1.w};
#pragma unroll
            for (int i = 0; i < 8; i++)
#pragma unroll
                for (int j = 0; j < 8; j++)
                    acc[i][j] += af[i] * bf[j];
        }
        __syncthreads();
    }

    // epilogue: add bias, write
#pragma unroll
    for (int i = 0; i < 8; i++) {
        const int m = m0 + ty * 8 + i;
#pragma unroll
        for (int jj = 0; jj < 2; jj++) {
            const int n = n0 + tx * 8 + jj * 4;
            float4 v;
            v.x = acc[i][jj * 4 + 0] + bias[n + 0];
            v.y = acc[i][jj * 4 + 1] + bias[n + 1];
            v.z = acc[i][jj * 4 + 2] + bias[n + 2];
            v.w = acc[i][jj * 4 + 3] + bias[n + 3];
            if (PHASE == 0) {
                *(float4*)&g_y[(size_t)m * 1024 + n] = v;
            } else {
                size_t dst;
                if (m < SPLIT_M) dst = (size_t)OUT_RC_BASE + (size_t)m * D_SZ + n;
                else             dst = (size_t)(m - SPLIT_M) * D_SZ + n;
                *(float4*)&outp[dst] = v;
            }
        }
    }
}

// ---------------- GLU: glu[m][d] = a * sigmoid(g) ----------------
__global__ void glu_kernel()
{
    size_t i = (size_t)blockIdx.x * blockDim.x + threadIdx.x;   // over M_ROWS*128 float4
    if (i >= (size_t)M_ROWS * 128) return;
    size_t m = i >> 7;
    int dq   = (int)(i & 127);
    const float4* Y = (const float4*)g_y;
    float4 a = Y[m * 256 + dq];
    float4 g = Y[m * 256 + 128 + dq];
    float4 o;
    o.x = a.x / (1.f + expf(-g.x));
    o.y = a.y / (1.f + expf(-g.y));
    o.z = a.z / (1.f + expf(-g.z));
    o.w = a.w / (1.f + expf(-g.w));
    ((float4*)g_glu)[m * 128 + dq] = o;
}

// ---------------- depthwise conv (utterance path) + SiLU-shift ----------------
// grid: (t_tile=32, d_chunk=4, b=16), block 128 (one d each)
__global__ __launch_bounds__(128) void dw_utt_kernel(
    const float* __restrict__ cache, const float* __restrict__ wd,
    const float* __restrict__ bd)
{
    __shared__ float xs[94][128];   // 64 outputs + 30 halo
    const int t0  = blockIdx.x * 64;
    const int d0  = blockIdx.y * 128;
    const int b   = blockIdx.z;
    const int tid = threadIdx.x;
    const int d   = d0 + tid;

    for (int r = 0; r < 94; r++) {
        const int p = t0 + r;                         // pad_utt time index
        float v;
        if (p < CS) v = cache[((size_t)b * D_SZ + d) * CS + p];
        else        v = g_glu[(((size_t)(R_LEN + p - CS)) * B_SZ + b) * D_SZ + d];
        xs[r][tid] = v;
    }
    __syncthreads();

    float w[KSZ];
#pragma unroll
    for (int k = 0; k < KSZ; k++) w[k] = wd[d * KSZ + k];
    const float bias = bd[d];

    for (int t = 0; t < 64; t++) {
        float acc = bias;
#pragma unroll
        for (int k = 0; k < KSZ; k++) acc += w[k] * xs[t + k][tid];
        const float z = acc / (1.f + expf(1.f - acc));      // acc * sigmoid(acc-1)
        g_z[(((size_t)(R_LEN + t0 + t)) * B_SZ + b) * D_SZ + d] = z;
    }
}

// ---------------- depthwise conv (right-context segments) + SiLU-shift ----------------
// grid: (chunk=64, b=16), block 512 (one d each)
__global__ __launch_bounds__(512) void dw_rc_kernel(
    const float* __restrict__ wd, const float* __restrict__ bd)
{
    const int c = blockIdx.x;
    const int b = blockIdx.y;
    const int d = threadIdx.x;

    float win[38];
#pragma unroll
    for (int j = 0; j < 38; j++) {
        // j<30: padding = pad_utt[(c+1)*32 + j] -> glu time 514 + 32c + j
        // j>=30: rc segment -> glu time c*8 + (j-30)
        const int tg = (j < CS) ? (514 + c * 32 + j) : (c * 8 + j - CS);
        win[j] = g_glu[(((size_t)tg) * B_SZ + b) * D_SZ + d];
    }
    float w[KSZ];
#pragma unroll
    for (int k = 0; k < KSZ; k++) w[k] = wd[d * KSZ + k];
    const float bias = bd[d];

#pragma unroll
    for (int r = 0; r < 8; r++) {
        float acc = bias;
#pragma unroll
        for (int k = 0; k < KSZ; k++) acc += w[k] * win[r + k];
        g_z[(((size_t)(c * 8 + r)) * B_SZ + b) * D_SZ + d] =
            acc / (1.f + expf(1.f - acc));
    }
}

// ---------------- new_cache copy ----------------
__global__ void cache_kernel(float* __restrict__ outp)
{
    const int i = blockIdx.x * blockDim.x + threadIdx.x;
    if (i >= B_SZ * D_SZ * CS) return;
    const int b   = i / (D_SZ * CS);
    const int rem = i % (D_SZ * CS);
    const int d   = rem / CS;
    const int j   = rem % CS;
    // pad_utt[:, :, 2048+j] = glu time (R + 2048 + j - 30) = 2530 + j
    outp[OUT_CACHE_BASE + i] =
        g_glu[(((size_t)(2530 + j)) * B_SZ + b) * D_SZ + d];
}

// ---------------- launch ----------------
extern "C" void kernel_launch(void* const* d_in, const int* in_sizes, int n_in,
                              void* d_out, int out_size)
{
    const float* utt   = (const float*)d_in[0];
    const float* rc    = (const float*)d_in[1];
    const float* cache = (const float*)d_in[2];
    const float* w1    = (const float*)d_in[3];
    const float* b1    = (const float*)d_in[4];
    const float* wd    = (const float*)d_in[5];
    const float* bd    = (const float*)d_in[6];
    const float* w2    = (const float*)d_in[7];
    const float* b2    = (const float*)d_in[8];
    float* out = (float*)d_out;

    // 1) pointwise conv1: y = x @ w1^T + b1
    dim3 g1(1024 / BN, M_ROWS / BM);
    sgemm_kernel<0><<<g1, 256>>>(rc, utt, w1, b1, nullptr);

    // 2) GLU
    {
        size_t total = (size_t)M_ROWS * 128;
        int blocks = (int)((total + 255) / 256);
        glu_kernel<<<blocks, 256>>>();
    }

    // 3) depthwise conv on utterance (with cache prefix), fused SiLU(x-1)
    dw_utt_kernel<<<dim3(U_LEN / 64, D_SZ / 128, B_SZ), 128>>>(cache, wd, bd);

    // 4) depthwise conv on right-context segments, fused SiLU(x-1)
    dw_rc_kernel<<<dim3(R_LEN / 8, B_SZ), 512>>>(wd, bd);

    // 5) pointwise conv2, writing split outputs directly
    dim3 g2(512 / BN, M_ROWS / BM);
    sgemm_kernel<1><<<g2, 256>>>(nullptr, nullptr, w2, b2, out);

    // 6) new_cache
    cache_kernel<<<(B_SZ * D_SZ * CS + 255) / 256, 256>>>(out);
}

// round 3
// speedup vs baseline: 2.0561x; 2.0561x over previous
#include <cuda_runtime.h>
#include <cuda_bf16.h>
#include <math.h>
#include <stdint.h>

// ---------------- problem constants ----------------
#define U_LEN   2048
#define B_SZ    16
#define D_SZ    512
#define R_LEN   512
#define M_ROWS  40960
#define CS      30
#define KSZ     31
#define SPLIT_M 8192

#define OUT_RC_BASE    16777216u     // U*B*D
#define OUT_CACHE_BASE 20971520u     // + R*B*D

// ---------------- scratch ----------------
__device__ float         g_glu[(size_t)M_ROWS * D_SZ];   // GLU output fp32 [t*b][d]
__device__ __nv_bfloat16 g_xh [(size_t)M_ROWS * D_SZ];   // input hi
__device__ __nv_bfloat16 g_xl [(size_t)M_ROWS * D_SZ];   // input lo
__device__ __nv_bfloat16 g_zh [(size_t)M_ROWS * D_SZ];   // post-dw hi
__device__ __nv_bfloat16 g_zl [(size_t)M_ROWS * D_SZ];   // post-dw lo
__device__ __nv_bfloat16 g_w1h[1024 * 512], g_w1l[1024 * 512];
__device__ __nv_bfloat16 g_w2h[512 * 512],  g_w2l[512 * 512];

// ---------------- asm helpers ----------------
__device__ __forceinline__ uint32_t smem_u32(const void* p) {
    uint32_t a;
    asm("{ .reg .u64 t; cvta.to.shared.u64 t, %1; cvt.u32.u64 %0, t; }" : "=r"(a) : "l"(p));
    return a;
}
#define CP_ASYNC16(dst, src) \
    asm volatile("cp.async.cg.shared.global [%0], [%1], 16;" :: "r"(dst), "l"(src) : "memory")
#define CP_COMMIT() asm volatile("cp.async.commit_group;" ::: "memory")
#define CP_WAIT2()  asm volatile("cp.async.wait_group 2;" ::: "memory")

#define LDSM4(r0, r1, r2, r3, addr)                                            \
    asm volatile("ldmatrix.sync.aligned.m8n8.x4.shared.b16 {%0,%1,%2,%3}, [%4];" \
                 : "=r"(r0), "=r"(r1), "=r"(r2), "=r"(r3) : "r"(addr))

#define MMA_BF16(d, a, b)                                                      \
    asm volatile("mma.sync.aligned.m16n8k16.row.col.f32.bf16.bf16.f32 "        \
                 "{%0,%1,%2,%3}, {%4,%5,%6,%7}, {%8,%9}, {%0,%1,%2,%3};"       \
                 : "+f"((d)[0]), "+f"((d)[1]), "+f"((d)[2]), "+f"((d)[3])      \
                 : "r"((a)[0]), "r"((a)[1]), "r"((a)[2]), "r"((a)[3]),         \
                   "r"((b)[0]), "r"((b)[1]))

// smem geometry: 4 tiles (Ah, Al, Bh, Bl), 128 rows x 32 bf16, row stride 40 bf16 (80B)
#define ROWSTRIDE_B 80
#define TILE_BYTES  10240            // 128 * 80
#define STAGE_BYTES 40960            // 4 tiles
#define NSTAGE      3
#define SMEM_TOTAL  (NSTAGE * STAGE_BYTES)

// ================= bf16 3-product tensor-core GEMM =================
// C[M,*] = A[M,512] @ W[*,512]^T (+bias in epilogue)
// PHASE 0: A = g_xh/g_xl, B rows interleaved (even=a-row n0+j/2, odd=g-row 512+n0+j/2)
//          epilogue: glu = (a+ba)*sigmoid(g+bg) -> g_glu (64 out cols / block)
// PHASE 1: A = g_zh/g_zl, W = w2, epilogue: +bias, split write to d_out (128 cols / block)
template<int PHASE>
__global__ void __launch_bounds__(256) tc_gemm_kernel(
    const float* __restrict__ bias, float* __restrict__ outp)
{
    extern __shared__ char smraw[];
    const uint32_t smem = smem_u32(smraw);

    const int tid  = threadIdx.x;
    const int wid  = tid >> 5;
    const int lane = tid & 31;
    const int wm   = wid >> 1;           // 0..3  (M warp)
    const int wn   = wid & 1;            // 0..1  (N warp)
    const int m0   = blockIdx.y * 128;
    const int bx   = blockIdx.x;

    // ---- per-thread cp.async descriptors (8 chunks of 16B per stage) ----
    const __nv_bfloat16* srcp[8];
    uint32_t dstoff[8];
#pragma unroll
    for (int i = 0; i < 8; i++) {
        const int tile = i >> 1;                      // 0:Ah 1:Al 2:Bh 3:Bl
        const int lc   = tid + 256 * (i & 1);
        const int r    = lc >> 2;                     // 0..127
        const int c    = lc & 3;                      // 16B chunk (8 bf16)
        dstoff[i] = tile * TILE_BYTES + r * ROWSTRIDE_B + c * 16;
        const __nv_bfloat16* base;
        size_t row;
        if (tile < 2) {                               // A tiles
            base = (tile == 0) ? ((PHASE == 0) ? g_xh : g_zh)
                               : ((PHASE == 0) ? g_xl : g_zl);
            row = (size_t)(m0 + r);
        } else {                                      // B tiles
            int wrow;
            if (PHASE == 0) {
                const int n0 = bx * 64;
                wrow = (r & 1) ? (512 + n0 + (r >> 1)) : (n0 + (r >> 1));
                base = (tile == 2) ? g_w1h : g_w1l;
            } else {
                wrow = bx * 128 + r;
                base = (tile == 2) ? g_w2h : g_w2l;
            }
            row = (size_t)wrow;
        }
        srcp[i] = base + row * 512 + c * 8;
    }

    // ---- ldmatrix base addresses ----
    uint32_t aBase[2][2];   // [hi/lo][mi]
#pragma unroll
    for (int h = 0; h < 2; h++)
#pragma unroll
        for (int mi = 0; mi < 2; mi++)
            aBase[h][mi] = smem + h * TILE_BYTES
                + (wm * 32 + mi * 16 + (lane & 15)) * ROWSTRIDE_B
                + ((lane >> 4) * 8) * 2;
    uint32_t bBase[2][4];   // [hi/lo][j] covering n-tiles (2j, 2j+1)
#pragma unroll
    for (int h = 0; h < 2; h++)
#pragma unroll
        for (int j = 0; j < 4; j++)
            bBase[h][j] = smem + (2 + h) * TILE_BYTES
                + (wn * 64 + 16 * j + ((lane >> 4) & 1) * 8 + (lane & 7)) * ROWSTRIDE_B
                + (((lane >> 3) & 1) * 8) * 2;

    float acc[2][8][4];
#pragma unroll
    for (int mi = 0; mi < 2; mi++)
#pragma unroll
        for (int ni = 0; ni < 8; ni++)
#pragma unroll
            for (int q = 0; q < 4; q++) acc[mi][ni][q] = 0.f;

    // ---- prologue: stages 0, 1 ----
#pragma unroll
    for (int pre = 0; pre < 2; pre++) {
#pragma unroll
        for (int i = 0; i < 8; i++)
            CP_ASYNC16(smem + pre * STAGE_BYTES + dstoff[i],
                       (const void*)(srcp[i] + pre * 32));
        CP_COMMIT();
    }

    // ---- main loop over K (16 iters of BK=32) ----
    for (int it = 0; it < 16; it++) {
        __syncthreads();                      // stage (it+2)%3 free to refill
        if (it + 2 < 16) {
            const uint32_t sb = ((it + 2) % NSTAGE) * STAGE_BYTES;
#pragma unroll
            for (int i = 0; i < 8; i++)
                CP_ASYNC16(smem + sb + dstoff[i],
                           (const void*)(srcp[i] + (it + 2) * 32));
        }
        CP_COMMIT();
        CP_WAIT2();                           // stage it complete
        __syncthreads();

        const uint32_t soffb = (it % NSTAGE) * STAGE_BYTES;
#pragma unroll
        for (int s = 0; s < 2; s++) {
            const uint32_t so = soffb + s * 32;
            uint32_t ah[2][4], al[2][4], bh[8][2], bl[8][2];
#pragma unroll
            for (int mi = 0; mi < 2; mi++) {
                LDSM4(ah[mi][0], ah[mi][1], ah[mi][2], ah[mi][3], aBase[0][mi] + so);
                LDSM4(al[mi][0], al[mi][1], al[mi][2], al[mi][3], aBase[1][mi] + so);
            }
#pragma unroll
            for (int j = 0; j < 4; j++) {
                LDSM4(bh[2*j][0], bh[2*j][1], bh[2*j+1][0], bh[2*j+1][1], bBase[0][j] + so);
                LDSM4(bl[2*j][0], bl[2*j][1], bl[2*j+1][0], bl[2*j+1][1], bBase[1][j] + so);
            }
#pragma unroll
            for (int mi = 0; mi < 2; mi++)
#pragma unroll
                for (int ni = 0; ni < 8; ni++) {
                    MMA_BF16(acc[mi][ni], ah[mi], bh[ni]);
                    MMA_BF16(acc[mi][ni], ah[mi], bl[ni]);
                    MMA_BF16(acc[mi][ni], al[mi], bh[ni]);
                }
        }
    }

    // ---- epilogue ----
    const int r0 = lane >> 2;   // 0..7
    const int cq = lane & 3;    // 0..3
    if (PHASE == 0) {
#pragma unroll
        for (int mi = 0; mi < 2; mi++) {
            const int mA = m0 + wm * 32 + mi * 16 + r0;
#pragma unroll
            for (int ni = 0; ni < 8; ni++) {
                const int cg = bx * 64 + wn * 32 + ni * 4 + cq;
                const float ba = bias[cg], bg = bias[512 + cg];
                float a0 = acc[mi][ni][0] + ba, g0 = acc[mi][ni][1] + bg;
                float a1 = acc[mi][ni][2] + ba, g1 = acc[mi][ni][3] + bg;
                g_glu[(size_t)mA * 512 + cg]       = a0 / (1.f + expf(-g0));
                g_glu[(size_t)(mA + 8) * 512 + cg] = a1 / (1.f + expf(-g1));
            }
        }
    } else {
#pragma unroll
        for (int mi = 0; mi < 2; mi++) {
            const int mA = m0 + wm * 32 + mi * 16 + r0;
#pragma unroll
            for (int ni = 0; ni < 8; ni++) {
                const int col = bx * 128 + wn * 64 + ni * 8 + 2 * cq;
                const float b0 = bias[col], b1 = bias[col + 1];
                float2 v0 = make_float2(acc[mi][ni][0] + b0, acc[mi][ni][1] + b1);
                float2 v1 = make_float2(acc[mi][ni][2] + b0, acc[mi][ni][3] + b1);
                size_t d0 = (mA < SPLIT_M)
                    ? ((size_t)OUT_RC_BASE + (size_t)mA * 512 + col)
                    : ((size_t)(mA - SPLIT_M) * 512 + col);
                size_t d1 = (mA + 8 < SPLIT_M)
                    ? ((size_t)OUT_RC_BASE + (size_t)(mA + 8) * 512 + col)
                    : ((size_t)(mA + 8 - SPLIT_M) * 512 + col);
                *(float2*)&outp[d0] = v0;
                *(float2*)&outp[d1] = v1;
            }
        }
    }
}

// ---------------- fp32 -> bf16 hi/lo conversions ----------------
__global__ void cvt_inputs_kernel(const float* __restrict__ utt,
                                  const float* __restrict__ rc)
{
    const size_t i = (size_t)blockIdx.x * blockDim.x + threadIdx.x;  // float4 units
    if (i >= (size_t)M_ROWS * 128) return;
    const size_t m = i >> 7;
    const int c4 = (int)(i & 127) * 4;
    const float* src = (m < SPLIT_M) ? (rc + m * 512 + c4)
                                     : (utt + (m - SPLIT_M) * 512 + c4);
    float4 v = *(const float4*)src;
    __nv_bfloat16 hx = __float2bfloat16(v.x), hy = __float2bfloat16(v.y);
    __nv_bfloat16 hz = __float2bfloat16(v.z), hw = __float2bfloat16(v.w);
    __nv_bfloat16 lx = __float2bfloat16(v.x - __bfloat162float(hx));
    __nv_bfloat16 ly = __float2bfloat16(v.y - __bfloat162float(hy));
    __nv_bfloat16 lz = __float2bfloat16(v.z - __bfloat162float(hz));
    __nv_bfloat16 lw = __float2bfloat16(v.w - __bfloat162float(hw));
    *(__nv_bfloat162*)&g_xh[m * 512 + c4]     = __nv_bfloat162(hx, hy);
    *(__nv_bfloat162*)&g_xh[m * 512 + c4 + 2] = __nv_bfloat162(hz, hw);
    *(__nv_bfloat162*)&g_xl[m * 512 + c4]     = __nv_bfloat162(lx, ly);
    *(__nv_bfloat162*)&g_xl[m * 512 + c4 + 2] = __nv_bfloat162(lz, lw);
}

__global__ void cvt_weights_kernel(const float* __restrict__ w1,
                                   const float* __restrict__ w2)
{
    const int i = blockIdx.x * blockDim.x + threadIdx.x;
    if (i >= 786432) return;
    float v; __nv_bfloat16 *ph, *pl; int off;
    if (i < 524288) { v = w1[i]; ph = g_w1h; pl = g_w1l; off = i; }
    else            { off = i - 524288; v = w2[off]; ph = g_w2h; pl = g_w2l; }
    __nv_bfloat16 h = __float2bfloat16(v);
    ph[off] = h;
    pl[off] = __float2bfloat16(v - __bfloat162float(h));
}

// ---------------- depthwise conv (utterance) + SiLU-shift -> zh/zl ----------------
__global__ __launch_bounds__(128) void dw_utt_kernel(
    const float* __restrict__ cache, const float* __restrict__ wd,
    const float* __restrict__ bd)
{
    __shared__ float xs[94][128];
    const int t0  = blockIdx.x * 64;
    const int d0  = blockIdx.y * 128;
    const int b   = blockIdx.z;
    const int tid = threadIdx.x;
    const int d   = d0 + tid;

    for (int rr = 0; rr < 94; rr++) {
        const int p = t0 + rr;
        float v;
        if (p < CS) v = cache[((size_t)b * D_SZ + d) * CS + p];
        else        v = g_glu[(((size_t)(R_LEN + p - CS)) * B_SZ + b) * D_SZ + d];
        xs[rr][tid] = v;
    }
    __syncthreads();

    float w[KSZ];
#pragma unroll
    for (int k = 0; k < KSZ; k++) w[k] = wd[d * KSZ + k];
    const float bb = bd[d];

    for (int t = 0; t < 64; t++) {
        float acc = bb;
#pragma unroll
        for (int k = 0; k < KSZ; k++) acc += w[k] * xs[t + k][tid];
        const float z = acc / (1.f + expf(1.f - acc));
        const size_t idx = (((size_t)(R_LEN + t0 + t)) * B_SZ + b) * D_SZ + d;
        __nv_bfloat16 h = __float2bfloat16(z);
        g_zh[idx] = h;
        g_zl[idx] = __float2bfloat16(z - __bfloat162float(h));
    }
}

// ---------------- depthwise conv (right-context) + SiLU-shift -> zh/zl ----------------
__global__ __launch_bounds__(512) void dw_rc_kernel(
    const float* __restrict__ wd, const float* __restrict__ bd)
{
    const int c = blockIdx.x;
    const int b = blockIdx.y;
    const int d = threadIdx.x;

    float win[38];
#pragma unroll
    for (int j = 0; j < 38; j++) {
        const int tg = (j < CS) ? (514 + c * 32 + j) : (c * 8 + j - CS);
        win[j] = g_glu[(((size_t)tg) * B_SZ + b) * D_SZ + d];
    }
    float w[KSZ];
#pragma unroll
    for (int k = 0; k < KSZ; k++) w[k] = wd[d * KSZ + k];
    const float bb = bd[d];

#pragma unroll
    for (int rr = 0; rr < 8; rr++) {
        float acc = bb;
#pragma unroll
        for (int k = 0; k < KSZ; k++) acc += w[k] * win[rr + k];
        const float z = acc / (1.f + expf(1.f - acc));
        const size_t idx = (((size_t)(c * 8 + rr)) * B_SZ + b) * D_SZ + d;
        __nv_bfloat16 h = __float2bfloat16(z);
        g_zh[idx] = h;
        g_zl[idx] = __float2bfloat16(z - __bfloat162float(h));
    }
}

// ---------------- new_cache copy ----------------
__global__ void cache_kernel(float* __restrict__ outp)
{
    const int i = blockIdx.x * blockDim.x + threadIdx.x;
    if (i >= B_SZ * D_SZ * CS) return;
    const int b   = i / (D_SZ * CS);
    const int rem = i % (D_SZ * CS);
    const int d   = rem / CS;
    const int j   = rem % CS;
    outp[OUT_CACHE_BASE + i] = g_glu[(((size_t)(2530 + j)) * B_SZ + b) * D_SZ + d];
}

// ---------------- launch ----------------
extern "C" void kernel_launch(void* const* d_in, const int* in_sizes, int n_in,
                              void* d_out, int out_size)
{
    const float* utt   = (const float*)d_in[0];
    const float* rc    = (const float*)d_in[1];
    const float* cache = (const float*)d_in[2];
    const float* w1    = (const float*)d_in[3];
    const float* b1    = (const float*)d_in[4];
    const float* wd    = (const float*)d_in[5];
    const float* bd    = (const float*)d_in[6];
    const float* w2    = (const float*)d_in[7];
    const float* b2    = (const float*)d_in[8];
    float* out = (float*)d_out;

    cudaFuncSetAttribute(tc_gemm_kernel<0>, cudaFuncAttributeMaxDynamicSharedMemorySize, SMEM_TOTAL);
    cudaFuncSetAttribute(tc_gemm_kernel<1>, cudaFuncAttributeMaxDynamicSharedMemorySize, SMEM_TOTAL);

    // 0) conversions
    cvt_weights_kernel<<<(786432 + 255) / 256, 256>>>(w1, w2);
    {
        size_t total = (size_t)M_ROWS * 128;
        cvt_inputs_kernel<<<(int)((total + 255) / 256), 256>>>(utt, rc);
    }

    // 1) pointwise conv1 + GLU fused epilogue -> g_glu
    tc_gemm_kernel<0><<<dim3(8, 320), 256, SMEM_TOTAL>>>(b1, nullptr);

    // 2) depthwise conv (utterance, cache prefix) + SiLU(x-1) -> g_zh/g_zl
    dw_utt_kernel<<<dim3(U_LEN / 64, D_SZ / 128, B_SZ), 128>>>(cache, wd, bd);

    // 3) depthwise conv (right-context segments) + SiLU(x-1) -> g_zh/g_zl
    dw_rc_kernel<<<dim3(R_LEN / 8, B_SZ), 512>>>(wd, bd);

    // 4) pointwise conv2 + bias, split outputs directly to d_out
    tc_gemm_kernel<1><<<dim3(4, 320), 256, SMEM_TOTAL>>>(b2, out);

    // 5) new_cache
    cache_kernel<<<(B_SZ * D_SZ * CS + 255) / 256, 256>>>(out);
}

// round 4
// speedup vs baseline: 2.2587x; 1.0986x over previous
#include <cuda_runtime.h>
#include <cuda_bf16.h>
#include <math.h>
#include <stdint.h>

// ---------------- problem constants ----------------
#define U_LEN   2048
#define B_SZ    16
#define D_SZ    512
#define R_LEN   512
#define M_ROWS  40960
#define CS      30
#define KSZ     31
#define SPLIT_M 8192

#define OUT_RC_BASE    16777216u     // U*B*D
#define OUT_CACHE_BASE 20971520u     // + R*B*D

// ---------------- scratch ----------------
__device__ float         g_glu[(size_t)M_ROWS * D_SZ];   // GLU output fp32 [t*b][d]
__device__ __nv_bfloat16 g_xh [(size_t)M_ROWS * D_SZ];   // input hi
__device__ __nv_bfloat16 g_xl [(size_t)M_ROWS * D_SZ];   // input lo
__device__ __nv_bfloat16 g_zh [(size_t)M_ROWS * D_SZ];   // post-dw hi
__device__ __nv_bfloat16 g_zl [(size_t)M_ROWS * D_SZ];   // post-dw lo
__device__ __nv_bfloat16 g_w1h[1024 * 512], g_w1l[1024 * 512];
__device__ __nv_bfloat16 g_w2h[512 * 512],  g_w2l[512 * 512];

// ---------------- asm helpers ----------------
__device__ __forceinline__ uint32_t smem_u32(const void* p) {
    uint32_t a;
    asm("{ .reg .u64 t; cvta.to.shared.u64 t, %1; cvt.u32.u64 %0, t; }" : "=r"(a) : "l"(p));
    return a;
}
#define CP_ASYNC16(dst, src) \
    asm volatile("cp.async.cg.shared.global [%0], [%1], 16;" :: "r"(dst), "l"(src) : "memory")
#define CP_COMMIT() asm volatile("cp.async.commit_group;" ::: "memory")
#define CP_WAIT2()  asm volatile("cp.async.wait_group 2;" ::: "memory")

#define LDSM4(r0, r1, r2, r3, addr)                                            \
    asm volatile("ldmatrix.sync.aligned.m8n8.x4.shared.b16 {%0,%1,%2,%3}, [%4];" \
                 : "=r"(r0), "=r"(r1), "=r"(r2), "=r"(r3) : "r"(addr))

#define MMA_BF16(d, a, b)                                                      \
    asm volatile("mma.sync.aligned.m16n8k16.row.col.f32.bf16.bf16.f32 "        \
                 "{%0,%1,%2,%3}, {%4,%5,%6,%7}, {%8,%9}, {%0,%1,%2,%3};"       \
                 : "+f"((d)[0]), "+f"((d)[1]), "+f"((d)[2]), "+f"((d)[3])      \
                 : "r"((a)[0]), "r"((a)[1]), "r"((a)[2]), "r"((a)[3]),         \
                   "r"((b)[0]), "r"((b)[1]))

// smem geometry: 4 tiles (Ah, Al, Bh, Bl), 128 rows x 32 bf16, row stride 40 bf16 (80B)
#define ROWSTRIDE_B 80
#define TILE_BYTES  10240            // 128 * 80
#define STAGE_BYTES 40960            // 4 tiles
#define NSTAGE      4
#define SMEM_TOTAL  (NSTAGE * STAGE_BYTES)

// ================= bf16 3-product tensor-core GEMM =================
// PHASE 0: A = g_xh/g_xl, B rows interleaved (even=a-row, odd=g-row)
//          epilogue: glu = (a+ba)*sigmoid(g+bg) -> g_glu (64 out cols / block)
// PHASE 1: A = g_zh/g_zl, W = w2, epilogue: +bias, split write to d_out
template<int PHASE>
__global__ void __launch_bounds__(256) tc_gemm_kernel(
    const float* __restrict__ bias, float* __restrict__ outp)
{
    extern __shared__ char smraw[];
    const uint32_t smem = smem_u32(smraw);

    const int tid  = threadIdx.x;
    const int wid  = tid >> 5;
    const int lane = tid & 31;
    const int wm   = wid >> 1;           // 0..3  (M warp)
    const int wn   = wid & 1;            // 0..1  (N warp)
    const int m0   = blockIdx.y * 128;
    const int bx   = blockIdx.x;

    // ---- per-thread cp.async descriptors (8 chunks of 16B per stage) ----
    const __nv_bfloat16* srcp[8];
    uint32_t dstoff[8];
#pragma unroll
    for (int i = 0; i < 8; i++) {
        const int tile = i >> 1;                      // 0:Ah 1:Al 2:Bh 3:Bl
        const int lc   = tid + 256 * (i & 1);
        const int r    = lc >> 2;                     // 0..127
        const int c    = lc & 3;                      // 16B chunk (8 bf16)
        dstoff[i] = tile * TILE_BYTES + r * ROWSTRIDE_B + c * 16;
        const __nv_bfloat16* base;
        size_t row;
        if (tile < 2) {                               // A tiles
            base = (tile == 0) ? ((PHASE == 0) ? g_xh : g_zh)
                               : ((PHASE == 0) ? g_xl : g_zl);
            row = (size_t)(m0 + r);
        } else {                                      // B tiles
            int wrow;
            if (PHASE == 0) {
                const int n0 = bx * 64;
                wrow = (r & 1) ? (512 + n0 + (r >> 1)) : (n0 + (r >> 1));
                base = (tile == 2) ? g_w1h : g_w1l;
            } else {
                wrow = bx * 128 + r;
                base = (tile == 2) ? g_w2h : g_w2l;
            }
            row = (size_t)wrow;
        }
        srcp[i] = base + row * 512 + c * 8;
    }

    // ---- ldmatrix base addresses ----
    uint32_t aBase[2][2];   // [hi/lo][mi]
#pragma unroll
    for (int h = 0; h < 2; h++)
#pragma unroll
        for (int mi = 0; mi < 2; mi++)
            aBase[h][mi] = smem + h * TILE_BYTES
                + (wm * 32 + mi * 16 + (lane & 15)) * ROWSTRIDE_B
                + ((lane >> 4) * 8) * 2;
    uint32_t bBase[2][4];   // [hi/lo][j] covering n-tiles (2j, 2j+1)
#pragma unroll
    for (int h = 0; h < 2; h++)
#pragma unroll
        for (int j = 0; j < 4; j++)
            bBase[h][j] = smem + (2 + h) * TILE_BYTES
                + (wn * 64 + 16 * j + ((lane >> 4) & 1) * 8 + (lane & 7)) * ROWSTRIDE_B
                + (((lane >> 3) & 1) * 8) * 2;

    float acc[2][8][4];
#pragma unroll
    for (int mi = 0; mi < 2; mi++)
#pragma unroll
        for (int ni = 0; ni < 8; ni++)
#pragma unroll
            for (int q = 0; q < 4; q++) acc[mi][ni][q] = 0.f;

    // ---- prologue: stages 0, 1, 2 ----
#pragma unroll
    for (int pre = 0; pre < 3; pre++) {
#pragma unroll
        for (int i = 0; i < 8; i++)
            CP_ASYNC16(smem + pre * STAGE_BYTES + dstoff[i],
                       (const void*)(srcp[i] + pre * 32));
        CP_COMMIT();
    }

    // ---- main loop: single __syncthreads per iter, 4-stage ring ----
    for (int it = 0; it < 16; it++) {
        CP_WAIT2();                           // stage it arrived
        __syncthreads();                      // all warps done reading stage it-1
        if (it + 3 < 16) {
            const uint32_t sb = ((it + 3) & 3) * STAGE_BYTES;
#pragma unroll
            for (int i = 0; i < 8; i++)
                CP_ASYNC16(smem + sb + dstoff[i],
                           (const void*)(srcp[i] + (it + 3) * 32));
        }
        CP_COMMIT();

        const uint32_t soffb = (it & 3) * STAGE_BYTES;
#pragma unroll
        for (int s = 0; s < 2; s++) {
            const uint32_t so = soffb + s * 32;
            uint32_t ah[2][4], al[2][4], bh[8][2], bl[8][2];
#pragma unroll
            for (int mi = 0; mi < 2; mi++) {
                LDSM4(ah[mi][0], ah[mi][1], ah[mi][2], ah[mi][3], aBase[0][mi] + so);
                LDSM4(al[mi][0], al[mi][1], al[mi][2], al[mi][3], aBase[1][mi] + so);
            }
#pragma unroll
            for (int j = 0; j < 4; j++) {
                LDSM4(bh[2*j][0], bh[2*j][1], bh[2*j+1][0], bh[2*j+1][1], bBase[0][j] + so);
                LDSM4(bl[2*j][0], bl[2*j][1], bl[2*j+1][0], bl[2*j+1][1], bBase[1][j] + so);
            }
#pragma unroll
            for (int mi = 0; mi < 2; mi++)
#pragma unroll
                for (int ni = 0; ni < 8; ni++) {
                    MMA_BF16(acc[mi][ni], ah[mi], bh[ni]);
                    MMA_BF16(acc[mi][ni], ah[mi], bl[ni]);
                    MMA_BF16(acc[mi][ni], al[mi], bh[ni]);
                }
        }
    }

    // ---- epilogue ----
    const int r0 = lane >> 2;   // 0..7
    const int cq = lane & 3;    // 0..3
    if (PHASE == 0) {
#pragma unroll
        for (int mi = 0; mi < 2; mi++) {
            const int mA = m0 + wm * 32 + mi * 16 + r0;
#pragma unroll
            for (int ni = 0; ni < 8; ni++) {
                const int cg = bx * 64 + wn * 32 + ni * 4 + cq;
                const float ba = bias[cg], bg = bias[512 + cg];
                float a0 = acc[mi][ni][0] + ba, g0 = acc[mi][ni][1] + bg;
                float a1 = acc[mi][ni][2] + ba, g1 = acc[mi][ni][3] + bg;
                g_glu[(size_t)mA * 512 + cg]       = a0 / (1.f + __expf(-g0));
                g_glu[(size_t)(mA + 8) * 512 + cg] = a1 / (1.f + __expf(-g1));
            }
        }
    } else {
#pragma unroll
        for (int mi = 0; mi < 2; mi++) {
            const int mA = m0 + wm * 32 + mi * 16 + r0;
#pragma unroll
            for (int ni = 0; ni < 8; ni++) {
                const int col = bx * 128 + wn * 64 + ni * 8 + 2 * cq;
                const float b0 = bias[col], b1 = bias[col + 1];
                float2 v0 = make_float2(acc[mi][ni][0] + b0, acc[mi][ni][1] + b1);
                float2 v1 = make_float2(acc[mi][ni][2] + b0, acc[mi][ni][3] + b1);
                size_t d0 = (mA < SPLIT_M)
                    ? ((size_t)OUT_RC_BASE + (size_t)mA * 512 + col)
                    : ((size_t)(mA - SPLIT_M) * 512 + col);
                size_t d1 = (mA + 8 < SPLIT_M)
                    ? ((size_t)OUT_RC_BASE + (size_t)(mA + 8) * 512 + col)
                    : ((size_t)(mA + 8 - SPLIT_M) * 512 + col);
                *(float2*)&outp[d0] = v0;
                *(float2*)&outp[d1] = v1;
            }
        }
    }
}

// ---------------- fp32 -> bf16 hi/lo conversions ----------------
__global__ void cvt_inputs_kernel(const float* __restrict__ utt,
                                  const float* __restrict__ rc)
{
    const size_t i = (size_t)blockIdx.x * blockDim.x + threadIdx.x;  // float4 units
    if (i >= (size_t)M_ROWS * 128) return;
    const size_t m = i >> 7;
    const int c4 = (int)(i & 127) * 4;
    const float* src = (m < SPLIT_M) ? (rc + m * 512 + c4)
                                     : (utt + (m - SPLIT_M) * 512 + c4);
    float4 v = *(const float4*)src;
    __nv_bfloat16 hx = __float2bfloat16(v.x), hy = __float2bfloat16(v.y);
    __nv_bfloat16 hz = __float2bfloat16(v.z), hw = __float2bfloat16(v.w);
    __nv_bfloat16 lx = __float2bfloat16(v.x - __bfloat162float(hx));
    __nv_bfloat16 ly = __float2bfloat16(v.y - __bfloat162float(hy));
    __nv_bfloat16 lz = __float2bfloat16(v.z - __bfloat162float(hz));
    __nv_bfloat16 lw = __float2bfloat16(v.w - __bfloat162float(hw));
    *(__nv_bfloat162*)&g_xh[m * 512 + c4]     = __nv_bfloat162(hx, hy);
    *(__nv_bfloat162*)&g_xh[m * 512 + c4 + 2] = __nv_bfloat162(hz, hw);
    *(__nv_bfloat162*)&g_xl[m * 512 + c4]     = __nv_bfloat162(lx, ly);
    *(__nv_bfloat162*)&g_xl[m * 512 + c4 + 2] = __nv_bfloat162(lz, lw);
}

__global__ void cvt_weights_kernel(const float* __restrict__ w1,
                                   const float* __restrict__ w2)
{
    const int i = blockIdx.x * blockDim.x + threadIdx.x;
    if (i >= 786432) return;
    float v; __nv_bfloat16 *ph, *pl; int off;
    if (i < 524288) { v = w1[i]; ph = g_w1h; pl = g_w1l; off = i; }
    else            { off = i - 524288; v = w2[off]; ph = g_w2h; pl = g_w2l; }
    __nv_bfloat16 h = __float2bfloat16(v);
    ph[off] = h;
    pl[off] = __float2bfloat16(v - __bfloat162float(h));
}

// ---------------- depthwise conv (utterance) + SiLU-shift -> zh/zl ----------------
// block: 256 thr = 128 d-lanes x 2 t-halves; t-tile 128 (+30 halo staged in smem)
__global__ __launch_bounds__(256) void dw_utt_kernel(
    const float* __restrict__ cache, const float* __restrict__ wd,
    const float* __restrict__ bd)
{
    __shared__ float xs[158][128];
    const int t0  = blockIdx.x * 128;
    const int d0  = blockIdx.y * 128;
    const int b   = blockIdx.z;
    const int tid = threadIdx.x;
    const int dl  = tid & 127;
    const int th  = tid >> 7;
    const int d   = d0 + dl;

    for (int i = tid; i < 158 * 128; i += 256) {
        const int rr = i >> 7;
        const int dd = d0 + (i & 127);
        const int p  = t0 + rr;                    // pad_utt time index
        float v;
        if (p < CS) v = cache[((size_t)b * D_SZ + dd) * CS + p];
        else        v = g_glu[(((size_t)(482 + p)) * B_SZ + b) * D_SZ + dd];
        xs[rr][i & 127] = v;
    }
    __syncthreads();

    float w[KSZ];
#pragma unroll
    for (int k = 0; k < KSZ; k++) w[k] = wd[d * KSZ + k];
    const float bb = bd[d];

#pragma unroll
    for (int g = 0; g < 8; g++) {
        const int tb = th * 64 + g * 8;
        float win[38];
#pragma unroll
        for (int j = 0; j < 38; j++) win[j] = xs[tb + j][dl];
#pragma unroll
        for (int r = 0; r < 8; r++) {
            float acc = bb;
#pragma unroll
            for (int k = 0; k < KSZ; k++) acc += w[k] * win[r + k];
            const float z = acc / (1.f + __expf(1.f - acc));
            const size_t idx = (((size_t)(R_LEN + t0 + tb + r)) * B_SZ + b) * D_SZ + d;
            __nv_bfloat16 h = __float2bfloat16(z);
            g_zh[idx] = h;
            g_zl[idx] = __float2bfloat16(z - __bfloat162float(h));
        }
    }
}

// ---------------- depthwise conv (right-context) + SiLU-shift -> zh/zl ----------------
__global__ __launch_bounds__(512) void dw_rc_kernel(
    const float* __restrict__ wd, const float* __restrict__ bd)
{
    const int c = blockIdx.x;
    const int b = blockIdx.y;
    const int d = threadIdx.x;

    float win[38];
#pragma unroll
    for (int j = 0; j < 38; j++) {
        const int tg = (j < CS) ? (514 + c * 32 + j) : (c * 8 + j - CS);
        win[j] = g_glu[(((size_t)tg) * B_SZ + b) * D_SZ + d];
    }
    float w[KSZ];
#pragma unroll
    for (int k = 0; k < KSZ; k++) w[k] = wd[d * KSZ + k];
    const float bb = bd[d];

#pragma unroll
    for (int rr = 0; rr < 8; rr++) {
        float acc = bb;
#pragma unroll
        for (int k = 0; k < KSZ; k++) acc += w[k] * win[rr + k];
        const float z = acc / (1.f + __expf(1.f - acc));
        const size_t idx = (((size_t)(c * 8 + rr)) * B_SZ + b) * D_SZ + d;
        __nv_bfloat16 h = __float2bfloat16(z);
        g_zh[idx] = h;
        g_zl[idx] = __float2bfloat16(z - __bfloat162float(h));
    }
}

// ---------------- new_cache copy ----------------
__global__ void cache_kernel(float* __restrict__ outp)
{
    const int i = blockIdx.x * blockDim.x + threadIdx.x;
    if (i >= B_SZ * D_SZ * CS) return;
    const int b   = i / (D_SZ * CS);
    const int rem = i % (D_SZ * CS);
    const int d   = rem / CS;
    const int j   = rem % CS;
    outp[OUT_CACHE_BASE + i] = g_glu[(((size_t)(2530 + j)) * B_SZ + b) * D_SZ + d];
}

// ---------------- launch ----------------
extern "C" void kernel_launch(void* const* d_in, const int* in_sizes, int n_in,
                              void* d_out, int out_size)
{
    const float* utt   = (const float*)d_in[0];
    const float* rc    = (const float*)d_in[1];
    const float* cache = (const float*)d_in[2];
    const float* w1    = (const float*)d_in[3];
    const float* b1    = (const float*)d_in[4];
    const float* wd    = (const float*)d_in[5];
    const float* bd    = (const float*)d_in[6];
    const float* w2    = (const float*)d_in[7];
    const float* b2    = (const float*)d_in[8];
    float* out = (float*)d_out;

    cudaFuncSetAttribute(tc_gemm_kernel<0>, cudaFuncAttributeMaxDynamicSharedMemorySize, SMEM_TOTAL);
    cudaFuncSetAttribute(tc_gemm_kernel<1>, cudaFuncAttributeMaxDynamicSharedMemorySize, SMEM_TOTAL);

    // 0) conversions
    cvt_weights_kernel<<<(786432 + 255) / 256, 256>>>(w1, w2);
    {
        size_t total = (size_t)M_ROWS * 128;
        cvt_inputs_kernel<<<(int)((total + 255) / 256), 256>>>(utt, rc);
    }

    // 1) pointwise conv1 + GLU fused epilogue -> g_glu
    tc_gemm_kernel<0><<<dim3(8, 320), 256, SMEM_TOTAL>>>(b1, nullptr);

    // 2) depthwise conv (utterance, cache prefix) + SiLU(x-1) -> g_zh/g_zl
    dw_utt_kernel<<<dim3(U_LEN / 128, D_SZ / 128, B_SZ), 256>>>(cache, wd, bd);

    // 3) depthwise conv (right-context segments) + SiLU(x-1) -> g_zh/g_zl
    dw_rc_kernel<<<dim3(R_LEN / 8, B_SZ), 512>>>(wd, bd);

    // 4) pointwise conv2 + bias, split outputs directly to d_out
    tc_gemm_kernel<1><<<dim3(4, 320), 256, SMEM_TOTAL>>>(b2, out);

    // 5) new_cache
    cache_kernel<<<(B_SZ * D_SZ * CS + 255) / 256, 256>>>(out);
}